// round 1
// baseline (speedup 1.0000x reference)
#include <cuda_runtime.h>
#include <cuda_bf16.h>
#include <cstdint>

// Problem constants
#define NUM_CHIPS 4
#define SEQ 1024
#define HIDDEN 2048
#define TOP_K 4
#define N_EXPERTS 32
#define MAX_TOK 1024
#define META_LEN 8
#define N_PER_CHIP (SEQ * TOP_K)          // 4096 assignments per chip
#define TOTAL_SLOTS (N_EXPERTS * MAX_TOK) // 32768
#define BUF_ELEMS ((size_t)TOTAL_SLOTS * HIDDEN)       // 67108864
#define META_OFF  BUF_ELEMS
#define CNT_OFF   (BUF_ELEMS + (size_t)TOTAL_SLOTS * META_LEN)

// Scratch (no allocations allowed)
__device__ int g_src[TOTAL_SLOTS];                 // slot -> global assignment id, or -1
__device__ int g_counts[NUM_CHIPS][N_EXPERTS];     // per-chip per-expert counts
__device__ int g_rank[NUM_CHIPS * N_PER_CHIP];     // rank within (chip, expert), stable order

// ---------------------------------------------------------------------------
// Kernel A: per-chip per-expert counts + stable rank of each assignment.
// One block per chip; warp w owns expert w. Also initializes g_src to -1.
// ---------------------------------------------------------------------------
__global__ void count_rank_kernel(const int* __restrict__ indices) {
    const int c    = blockIdx.x;
    const int warp = threadIdx.x >> 5;   // expert id (0..31)
    const int lane = threadIdx.x & 31;

    // init src map (4 blocks x 1024 threads x 8 = 32768)
#pragma unroll
    for (int j = 0; j < 8; j++)
        g_src[c * 8192 + j * 1024 + threadIdx.x] = -1;

    const int* idx = indices + c * N_PER_CHIP;
    const unsigned lt_mask = (1u << lane) - 1u;
    int base = 0;
    for (int i = 0; i < N_PER_CHIP; i += 32) {
        int v = idx[i + lane];
        bool p = (v == warp);
        unsigned m = __ballot_sync(0xFFFFFFFFu, p);
        if (p) g_rank[c * N_PER_CHIP + i + lane] = base + __popc(m & lt_mask);
        base += __popc(m);
    }
    if (lane == 0) g_counts[c][warp] = base;
}

// ---------------------------------------------------------------------------
// Kernel B: destination slot per assignment -> inverse map g_src[slot].
// Also emits the 32 expert counters (as float) to the output tail.
// ---------------------------------------------------------------------------
__global__ void plan_kernel(const int* __restrict__ indices, float* __restrict__ out) {
    int tid = blockIdx.x * blockDim.x + threadIdx.x;   // 0..16383
    int c = tid >> 12;
    int e = indices[tid];

    int off = 0;
#pragma unroll
    for (int cc = 0; cc < NUM_CHIPS; cc++)
        if (cc < c) off += g_counts[cc][e];

    int slot = e * MAX_TOK + off + g_rank[tid];
    g_src[slot] = tid;

    if (tid < N_EXPERTS) {
        int tot = g_counts[0][tid] + g_counts[1][tid] + g_counts[2][tid] + g_counts[3][tid];
        out[CNT_OFF + tid] = (float)tot;
    }
}

// ---------------------------------------------------------------------------
// Kernel C: one block per slot. Copy the token's 2048-float row (or zeros)
// and write the 8 metadata words (or -1s). Every output byte written once.
// ---------------------------------------------------------------------------
__global__ void __launch_bounds__(256) gather_kernel(const float* __restrict__ x,
                                                     const float* __restrict__ w,
                                                     const int* __restrict__ indices,
                                                     float* __restrict__ out) {
    const int slot = blockIdx.x;
    const int a = g_src[slot];
    const int t = threadIdx.x;
    float4* dst = reinterpret_cast<float4*>(out + (size_t)slot * HIDDEN);

    if (a >= 0) {
        const int c   = a >> 12;
        const int n   = a & (N_PER_CHIP - 1);
        const int tok = n >> 2;
        const float4* src =
            reinterpret_cast<const float4*>(x + ((size_t)c * SEQ + tok) * HIDDEN);
        float4 v0 = src[t];
        float4 v1 = src[t + 256];
        dst[t]       = v0;
        dst[t + 256] = v1;
        if (t == 0) {
            float* md = out + META_OFF + (size_t)slot * META_LEN;
            __nv_bfloat16 hb = __float2bfloat16(w[a]);
            unsigned short bits = __bfloat16_as_ushort(hb);
            md[0] = (float)c;
            md[1] = (float)tok;
            md[2] = (float)(n & 3);
            md[3] = (float)indices[a];
            md[4] = (float)bits;
            md[5] = 0.0f; md[6] = 0.0f; md[7] = 0.0f;
        }
    } else {
        const float4 z = make_float4(0.f, 0.f, 0.f, 0.f);
        dst[t]       = z;
        dst[t + 256] = z;
        if (t == 0) {
            float* md = out + META_OFF + (size_t)slot * META_LEN;
#pragma unroll
            for (int j = 0; j < META_LEN; j++) md[j] = -1.0f;
        }
    }
}

// ---------------------------------------------------------------------------
extern "C" void kernel_launch(void* const* d_in, const int* in_sizes, int n_in,
                              void* d_out, int out_size) {
    const float* x   = (const float*)d_in[0];   // [4,1024,2048] f32
    const float* wts = (const float*)d_in[1];   // [4,1024,4]    f32
    const int*   ind = (const int*)  d_in[2];   // [4,1024,4]    i32
    float* out = (float*)d_out;

    count_rank_kernel<<<NUM_CHIPS, 1024>>>(ind);
    plan_kernel<<<(NUM_CHIPS * N_PER_CHIP) / 256, 256>>>(ind, out);
    gather_kernel<<<TOTAL_SLOTS, 256>>>(x, wts, ind, out);
}

// round 2
// speedup vs baseline: 1.0235x; 1.0235x over previous
#include <cuda_runtime.h>
#include <cuda_bf16.h>
#include <cstdint>

// Problem constants
#define NUM_CHIPS 4
#define SEQ 1024
#define HIDDEN 2048
#define TOP_K 4
#define N_EXPERTS 32
#define MAX_TOK 1024
#define META_LEN 8
#define N_PER_CHIP (SEQ * TOP_K)           // 4096 assignments per chip
#define N_TOTAL (NUM_CHIPS * N_PER_CHIP)   // 16384 assignments
#define N_CHUNKS (N_TOTAL / 32)            // 512 warp-chunks (chip-major order)
#define TOTAL_SLOTS (N_EXPERTS * MAX_TOK)  // 32768
#define BUF_ELEMS ((size_t)TOTAL_SLOTS * HIDDEN)      // 67108864
#define META_OFF  BUF_ELEMS
#define CNT_OFF   (BUF_ELEMS + (size_t)TOTAL_SLOTS * META_LEN)

// Scratch (no allocations allowed)
__device__ int g_src[TOTAL_SLOTS];                    // slot -> assignment id, or -1
__device__ int g_rank[N_TOTAL];                       // rank within its warp-chunk's expert group
__device__ int g_wcount[N_EXPERTS][N_CHUNKS];         // per-expert per-chunk counts
__device__ int g_chunk_off[N_EXPERTS][N_CHUNKS];      // exclusive offset of chunk within expert

// ---------------------------------------------------------------------------
// Kernel A: per-warp-chunk expert counts + stable within-chunk rank via
// __match_any_sync (single-instruction grouping). Also init g_src = -1.
// ---------------------------------------------------------------------------
__global__ void __launch_bounds__(1024) rank_count_kernel(const int* __restrict__ idx) {
    const int a    = blockIdx.x * 1024 + threadIdx.x;  // 0..16383, chip-major
    const int lane = threadIdx.x & 31;
    const int wchunk = a >> 5;                          // global chunk id 0..511

    // init inverse map (16 blocks x 1024 x 2 = 32768)
    g_src[a]           = -1;
    g_src[a + N_TOTAL] = -1;

    // zero this chunk's count column (warp-cooperative, then barrier)
    g_wcount[lane][wchunk] = 0;
    __syncwarp();

    const int v = idx[a];
    const unsigned m = __match_any_sync(0xFFFFFFFFu, v);
    const unsigned lt = (1u << lane) - 1u;
    g_rank[a] = __popc(m & lt);
    if ((m & lt) == 0)                    // group leader (lowest lane with this expert)
        g_wcount[v][wchunk] = __popc(m);
}

// ---------------------------------------------------------------------------
// Kernel B: warp e scans expert e's 512 chunk counts (chip-major order gives
// the reference's chip0..chip3 serialization). Emits exclusive chunk offsets
// and the 32 expert counters.
// ---------------------------------------------------------------------------
__global__ void __launch_bounds__(1024) scan_kernel(float* __restrict__ out) {
    const int e    = threadIdx.x >> 5;
    const int lane = threadIdx.x & 31;
    int carry = 0;
#pragma unroll
    for (int i = 0; i < N_CHUNKS / 32; i++) {
        const int ch  = i * 32 + lane;
        const int cnt = g_wcount[e][ch];
        int s = cnt;
#pragma unroll
        for (int d = 1; d < 32; d <<= 1) {
            int t = __shfl_up_sync(0xFFFFFFFFu, s, d);
            if (lane >= d) s += t;
        }
        g_chunk_off[e][ch] = carry + s - cnt;
        carry += __shfl_sync(0xFFFFFFFFu, s, 31);
    }
    if (lane == 0) out[CNT_OFF + e] = (float)carry;
}

// ---------------------------------------------------------------------------
// Kernel C: slot per assignment -> inverse map.
// ---------------------------------------------------------------------------
__global__ void __launch_bounds__(256) plan_kernel(const int* __restrict__ idx) {
    const int a = blockIdx.x * 256 + threadIdx.x;
    const int e = idx[a];
    const int slot = e * MAX_TOK + g_chunk_off[e][a >> 5] + g_rank[a];
    g_src[slot] = a;
}

// ---------------------------------------------------------------------------
// Kernel D: one block per slot; copy token row (or zeros) + 8 meta words.
// Every output byte written exactly once (buffer is poisoned pre-run).
// ---------------------------------------------------------------------------
__global__ void __launch_bounds__(256) gather_kernel(const float* __restrict__ x,
                                                     const float* __restrict__ w,
                                                     const int* __restrict__ indices,
                                                     float* __restrict__ out) {
    const int slot = blockIdx.x;
    const int a = g_src[slot];
    const int t = threadIdx.x;
    float4* dst = reinterpret_cast<float4*>(out + (size_t)slot * HIDDEN);

    if (a >= 0) {
        const int c   = a >> 12;
        const int n   = a & (N_PER_CHIP - 1);
        const int tok = n >> 2;
        const float4* src =
            reinterpret_cast<const float4*>(x + ((size_t)c * SEQ + tok) * HIDDEN);
        float4 v0 = src[t];
        float4 v1 = src[t + 256];
        dst[t]       = v0;
        dst[t + 256] = v1;
        if (t == 0) {
            float* md = out + META_OFF + (size_t)slot * META_LEN;
            __nv_bfloat16 hb = __float2bfloat16(w[a]);
            unsigned short bits = __bfloat16_as_ushort(hb);
            md[0] = (float)c;
            md[1] = (float)tok;
            md[2] = (float)(n & 3);
            md[3] = (float)indices[a];
            md[4] = (float)bits;
            md[5] = 0.0f; md[6] = 0.0f; md[7] = 0.0f;
        }
    } else {
        const float4 z = make_float4(0.f, 0.f, 0.f, 0.f);
        dst[t]       = z;
        dst[t + 256] = z;
        if (t == 0) {
            float* md = out + META_OFF + (size_t)slot * META_LEN;
#pragma unroll
            for (int j = 0; j < META_LEN; j++) md[j] = -1.0f;
        }
    }
}

// ---------------------------------------------------------------------------
extern "C" void kernel_launch(void* const* d_in, const int* in_sizes, int n_in,
                              void* d_out, int out_size) {
    const float* x   = (const float*)d_in[0];   // [4,1024,2048] f32
    const float* wts = (const float*)d_in[1];   // [4,1024,4]    f32
    const int*   ind = (const int*)  d_in[2];   // [4,1024,4]    i32
    float* out = (float*)d_out;

    rank_count_kernel<<<N_TOTAL / 1024, 1024>>>(ind);
    scan_kernel<<<1, 1024>>>(out);
    plan_kernel<<<N_TOTAL / 256, 256>>>(ind);
    gather_kernel<<<TOTAL_SLOTS, 256>>>(x, wts, ind, out);
}